// round 15
// baseline (speedup 1.0000x reference)
#include <cuda_runtime.h>
#include <cuda_fp16.h>
#include <cstdint>

#define NROWS 8192
#define NCH   256

// ---- GEMM1 (small) tiling ----
#define BM 128
#define BN 128
#define BK 64
#define NTHREADS 256
#define STAGE_BYTES 32768
#define SMEM_SZ (2 * STAGE_BYTES)

// ---- GEMM2 (big) tiling: 128x128 tile, full K, N-split ----
#define BM2 128
#define BN2 128
#define BK2 64
#define NTH2 512
#define NSTG 4
#define STG2 32768                 // A 16KB + B 16KB
#define SMEM2 (NSTG * STG2 + 128)  // stages + mbarriers

// ---------------- device scratch ----------------
__device__ __half g_WhT[NCH * NCH];            // W^T fp16 [n][k]
__device__ __half g_BhT[(size_t)NCH * NROWS];  // B^T fp16 [n][m]

// ---------------- PTX helpers ----------------
__device__ __forceinline__ uint32_t cvta_smem(const void* p) {
    uint32_t a;
    asm("{ .reg .u64 t; cvta.to.shared.u64 t, %1; cvt.u32.u64 %0, t; }"
        : "=r"(a) : "l"(p));
    return a;
}
__device__ __forceinline__ uint32_t elect_one() {
    uint32_t r;
    asm volatile("{ .reg .pred p; elect.sync _|p, 0xFFFFFFFF; selp.b32 %0,1,0,p; }"
                 : "=r"(r));
    return r;
}
__device__ __forceinline__ void cp16(uint32_t saddr, const void* gaddr) {
    asm volatile("cp.async.cg.shared.global [%0], [%1], 16;"
                 :: "r"(saddr), "l"(gaddr) : "memory");
}
__device__ __forceinline__ void cp_commit() {
    asm volatile("cp.async.commit_group;" ::: "memory");
}
__device__ __forceinline__ void cp_wait0() {
    asm volatile("cp.async.wait_group 0;" ::: "memory");
}
__device__ __forceinline__ void cp_wait1() {
    asm volatile("cp.async.wait_group 1;" ::: "memory");
}
__device__ __forceinline__ void mbar_init(uint32_t m, uint32_t cnt) {
    asm volatile("mbarrier.init.shared.b64 [%0], %1;" :: "r"(m), "r"(cnt) : "memory");
}
__device__ __forceinline__ void mbar_arrive(uint32_t m) {
    asm volatile("{ .reg .b64 st; mbarrier.arrive.shared.b64 st, [%0]; }"
                 :: "r"(m) : "memory");
}
__device__ __forceinline__ void mbar_wait(uint32_t m, uint32_t parity) {
    asm volatile(
        "{\n\t.reg .pred P;\n"
        "LW_%=:\n\t"
        "mbarrier.try_wait.parity.acquire.cta.shared::cta.b64 P, [%0], %1, 0x989680;\n\t"
        "@P bra.uni LD_%=;\n\t"
        "bra.uni LW_%=;\n"
        "LD_%=:\n\t}"
        :: "r"(m), "r"(parity) : "memory");
}
__device__ __forceinline__ void ldmx4(uint32_t* r, uint32_t addr) {
    asm volatile("ldmatrix.sync.aligned.m8n8.x4.shared.b16 {%0,%1,%2,%3}, [%4];"
                 : "=r"(r[0]), "=r"(r[1]), "=r"(r[2]), "=r"(r[3]) : "r"(addr));
}
__device__ __forceinline__ void mma16816(float* c, const uint32_t* a,
                                         uint32_t b0, uint32_t b1) {
    asm volatile(
        "mma.sync.aligned.m16n8k16.row.col.f32.f16.f16.f32 "
        "{%0,%1,%2,%3}, {%4,%5,%6,%7}, {%8,%9}, {%0,%1,%2,%3};"
        : "+f"(c[0]), "+f"(c[1]), "+f"(c[2]), "+f"(c[3])
        : "r"(a[0]), "r"(a[1]), "r"(a[2]), "r"(a[3]), "r"(b0), "r"(b1));
}
__device__ __forceinline__ void sts128(uint32_t addr, uint32_t x, uint32_t y,
                                       uint32_t z, uint32_t w) {
    asm volatile("st.shared.v4.b32 [%0], {%1,%2,%3,%4};"
                 :: "r"(addr), "r"(x), "r"(y), "r"(z), "r"(w) : "memory");
}
// refined rsqrt of D's diagonal element i
__device__ __forceinline__ float dval(const float* __restrict__ D, int i) {
    float x = D[(size_t)i * (NROWS + 1)];
    float r = rsqrtf(x);
    return r * (1.5f - 0.5f * x * r * r);
}

// ---------------- W^T transpose (coalesced both ways) ----------------
__global__ void transposeW_kernel(const float* __restrict__ W) {
    __shared__ float tile[32][33];
    const int bx = blockIdx.x & 7;    // n-tile
    const int by = blockIdx.x >> 3;   // k-tile
    const int x  = threadIdx.x & 31;
    const int y0 = (threadIdx.x >> 5) * 4;
#pragma unroll
    for (int i = 0; i < 4; ++i)
        tile[y0 + i][x] = W[(by * 32 + y0 + i) * NCH + bx * 32 + x];
    __syncthreads();
#pragma unroll
    for (int i = 0; i < 4; ++i)
        g_WhT[(bx * 32 + y0 + i) * NCH + by * 32 + x] =
            __float2half_rn(tile[x][y0 + i]);
}

// ---------------------------------------------------------------------------
// GEMM1 (2-stage lockstep): BhT[n][m] = d[m]*(W^T @ H^T)[n][m]
// ---------------------------------------------------------------------------
__global__ __launch_bounds__(NTHREADS, 1)
void gemm1_hmma(const float* __restrict__ f32op, int ld32,
                const __half* __restrict__ f16op, int ld16,
                int ktiles, __half* __restrict__ dsth,
                const float* __restrict__ D) {
    extern __shared__ __align__(16) char smem_raw[];
    __shared__ float s_d[BN];
    const uint32_t smem = cvta_smem(smem_raw);

    const int tid  = threadIdx.x;
    const int lane = tid & 31;
    const int wid  = tid >> 5;
    const int wm   = (wid & 1) * 64;
    const int wn   = (wid >> 1) * 32;

    const int m0 = blockIdx.y * BM;   // n-channel dim
    const int n0 = blockIdx.x * BN;   // node dim

    if (tid < BN) s_d[tid] = dval(D, n0 + tid);

    const uint32_t off32 = 16384u;
    const uint32_t off16 = 0u;

    const int lrow = tid >> 1;
    const int lseg = tid & 1;
    const float* g32 = f32op + (size_t)(n0 + lrow) * ld32 + lseg * 32;
    const __half* g16 = f16op + (size_t)(m0 + lrow) * ld16 + lseg * 32;
    const uint32_t srow = (uint32_t)lrow * 128u;
    const int rmask = lrow & 7;

    float4 pf[8];

#define LDG32(t)                                                               \
    do {                                                                       \
        const float4* p = (const float4*)(g32 + (size_t)(t) * BK);             \
        _Pragma("unroll") for (int j = 0; j < 8; ++j) pf[j] = __ldg(p + j);    \
    } while (0)
#define STS32(stg)                                                             \
    do {                                                                       \
        uint32_t db = smem + (stg) * STAGE_BYTES + off32 + srow;               \
        _Pragma("unroll") for (int c = 0; c < 4; ++c) {                        \
            __half2 h0 = __floats2half2_rn(pf[2 * c].x, pf[2 * c].y);          \
            __half2 h1 = __floats2half2_rn(pf[2 * c].z, pf[2 * c].w);          \
            __half2 h2 = __floats2half2_rn(pf[2 * c + 1].x, pf[2 * c + 1].y);  \
            __half2 h3 = __floats2half2_rn(pf[2 * c + 1].z, pf[2 * c + 1].w);  \
            uint32_t ch = (uint32_t)((lseg * 4 + c) ^ rmask);                  \
            sts128(db + ch * 16u, *(uint32_t*)&h0, *(uint32_t*)&h1,            \
                   *(uint32_t*)&h2, *(uint32_t*)&h3);                          \
        }                                                                      \
    } while (0)
#define CP16T(t, stg)                                                          \
    do {                                                                       \
        uint32_t db = smem + (stg) * STAGE_BYTES + off16 + srow;               \
        const __half* p = g16 + (size_t)(t) * BK;                              \
        _Pragma("unroll") for (int j = 0; j < 4; ++j) {                        \
            uint32_t ch = (uint32_t)((lseg * 4 + j) ^ rmask);                  \
            cp16(db + ch * 16u, p + j * 8);                                    \
        }                                                                      \
    } while (0)

    float acc[4][4][4];
#pragma unroll
    for (int i = 0; i < 4; ++i)
#pragma unroll
        for (int j = 0; j < 4; ++j)
#pragma unroll
            for (int q = 0; q < 4; ++q) acc[i][j][q] = 0.0f;

    const int lr8 = (lane & 7) + ((lane >> 3) & 1) * 8;
    uint32_t rowA[4], rowB[2];
#pragma unroll
    for (int mt = 0; mt < 4; ++mt) rowA[mt] = (uint32_t)(wm + mt * 16 + lr8) * 128u;
#pragma unroll
    for (int i = 0; i < 2; ++i) rowB[i] = (uint32_t)(wn + i * 16 + lr8) * 128u;
    const uint32_t lmask = (uint32_t)(lane & 7);
    const uint32_t khalf = (uint32_t)(lane >> 4);

#define COMPUTE1(stg)                                                          \
    do {                                                                       \
        uint32_t sa = smem + (stg) * STAGE_BYTES + off16;                      \
        uint32_t sb = smem + (stg) * STAGE_BYTES + off32;                      \
        _Pragma("unroll") for (int ks = 0; ks < 4; ++ks) {                     \
            uint32_t pa = ((ks * 2 + khalf) ^ lmask) * 16u;                    \
            uint32_t a[4][4], b[2][4];                                         \
            _Pragma("unroll") for (int mt = 0; mt < 4; ++mt)                   \
                ldmx4(a[mt], sa + rowA[mt] + pa);                              \
            _Pragma("unroll") for (int i = 0; i < 2; ++i)                      \
                ldmx4(b[i], sb + rowB[i] + pa);                                \
            _Pragma("unroll") for (int mt = 0; mt < 4; ++mt)                   \
                _Pragma("unroll") for (int j = 0; j < 4; ++j)                  \
                    mma16816(acc[mt][j], a[mt], b[j >> 1][j & 1],              \
                             b[j >> 1][2 + (j & 1)]);                          \
        }                                                                      \
    } while (0)

    const int T = ktiles;
    LDG32(0);
    CP16T(0, 0);
    cp_commit();
    STS32(0);
    if (T > 1) LDG32(1);
    cp_wait0();
    __syncthreads();

    int s = 0;
    for (int t = 0; t < T; ++t) {
        if (t + 1 < T) { CP16T(t + 1, s ^ 1); cp_commit(); }
        COMPUTE1(s);
        if (t + 1 < T) {
            STS32(s ^ 1);
            if (t + 2 < T) LDG32(t + 2);
            cp_wait0();
        }
        __syncthreads();
        s ^= 1;
    }

    const int er = lane >> 2;
    const int ec = (lane & 3) * 2;
#pragma unroll
    for (int mt = 0; mt < 4; ++mt) {
        const int r0 = m0 + wm + mt * 16 + er;
#pragma unroll
        for (int j = 0; j < 4; ++j) {
            const int cl = wn + j * 8 + ec;         // local node col in [0,BN)
            const int c  = n0 + cl;
            float* a = acc[mt][j];
            float s0 = s_d[cl], s1 = s_d[cl + 1];
            __half2 h0 = __floats2half2_rn(a[0] * s0, a[1] * s1);
            __half2 h1 = __floats2half2_rn(a[2] * s0, a[3] * s1);
            *(__half2*)(dsth + (size_t)r0 * NROWS + c) = h0;
            *(__half2*)(dsth + (size_t)(r0 + 8) * NROWS + c) = h1;
        }
    }
#undef LDG32
#undef STS32
#undef CP16T
#undef COMPUTE1
}

// ---------------------------------------------------------------------------
// GEMM2: 128x128 CTA tile, FULL K=8192, N-split grid (64 m-tiles x 2 n-halves).
// 512 threads, 16 warps of 32x32, 4-stage mbarrier pipeline, full-iteration
// A prefetch distance. Writes out directly with d[m] row scale (no partials,
// no reduce kernel).
// ---------------------------------------------------------------------------
__global__ __launch_bounds__(NTH2, 1)
void gemm2_hmma(const float* __restrict__ A, const float* __restrict__ D,
                float* __restrict__ out) {
    extern __shared__ __align__(16) char smem_raw[];
    __shared__ float s_d[BM2];
    const uint32_t smem = cvta_smem(smem_raw);
    const uint32_t mb = smem + NSTG * STG2;   // full[s]=mb+16s, empty[s]=+16s+8

    const int tid  = threadIdx.x;
    const int lane = tid & 31;
    const int wid  = tid >> 5;               // 0..15
    const int wm   = (wid & 3) * 32;         // 4 warps in M
    const int wn   = (wid >> 2) * 32;        // 4 warps in N

    const int m0 = blockIdx.x * BM2;
    const int n0 = blockIdx.y * BN2;

    if (tid < BM2) s_d[tid] = dval(D, m0 + tid);
    if (tid == 0) {
#pragma unroll
        for (int s = 0; s < NSTG; ++s) {
            mbar_init(mb + 16 * s, 16);      // full: 16 warp arrivals
            mbar_init(mb + 16 * s + 8, 16);  // empty: 16 warp arrivals
        }
    }
    __syncthreads();

    // A loader: 4 threads/row (128 rows), each 16 floats (4 x float4)
    const int row = tid >> 2;                // 0..127
    const int q   = tid & 3;
    const float* gA = A + (size_t)(m0 + row) * NROWS + q * 16;
    const uint32_t arow_off = (uint32_t)row * 128u;
    const int rmask = row & 7;

    // B loader: 4 threads/row (128 rows of BhT n-half), each 2 x 16B chunks
    const __half* gB = g_BhT + (size_t)(n0 + row) * NROWS + q * 16;
    const uint32_t brow_off = 16384u + (uint32_t)row * 128u;

    float4 pf[4];

#define LDGA(t)                                                                \
    do {                                                                       \
        const float4* p = (const float4*)(gA + (size_t)(t) * BK2);             \
        _Pragma("unroll") for (int j = 0; j < 4; ++j) pf[j] = __ldg(p + j);    \
    } while (0)
#define STSA(stg)                                                              \
    do {                                                                       \
        uint32_t db = smem + (stg) * STG2 + arow_off;                          \
        _Pragma("unroll") for (int c = 0; c < 2; ++c) {                        \
            __half2 h0 = __floats2half2_rn(pf[2 * c].x, pf[2 * c].y);          \
            __half2 h1 = __floats2half2_rn(pf[2 * c].z, pf[2 * c].w);          \
            __half2 h2 = __floats2half2_rn(pf[2 * c + 1].x, pf[2 * c + 1].y);  \
            __half2 h3 = __floats2half2_rn(pf[2 * c + 1].z, pf[2 * c + 1].w);  \
            uint32_t ch = (uint32_t)((q * 2 + c) ^ rmask);                     \
            sts128(db + ch * 16u, *(uint32_t*)&h0, *(uint32_t*)&h1,            \
                   *(uint32_t*)&h2, *(uint32_t*)&h3);                          \
        }                                                                      \
    } while (0)
#define CPB(stg, t)                                                            \
    do {                                                                       \
        uint32_t db = smem + (stg) * STG2 + brow_off;                          \
        const __half* p = gB + (size_t)(t) * BK2;                              \
        _Pragma("unroll") for (int j = 0; j < 2; ++j) {                        \
            uint32_t ch = (uint32_t)((q * 2 + j) ^ rmask);                     \
            cp16(db + ch * 16u, p + j * 8);                                    \
        }                                                                      \
    } while (0)

    float acc[2][4][4];
#pragma unroll
    for (int i = 0; i < 2; ++i)
#pragma unroll
        for (int j = 0; j < 4; ++j)
#pragma unroll
            for (int qq = 0; qq < 4; ++qq) acc[i][j][qq] = 0.0f;

    const int lr8 = (lane & 7) + ((lane >> 3) & 1) * 8;
    uint32_t rowA[2], rowB[2];
#pragma unroll
    for (int mt = 0; mt < 2; ++mt) rowA[mt] = (uint32_t)(wm + mt * 16 + lr8) * 128u;
#pragma unroll
    for (int i = 0; i < 2; ++i)
        rowB[i] = 16384u + (uint32_t)(wn + i * 16 + lr8) * 128u;
    const uint32_t lmask = (uint32_t)(lane & 7);
    const uint32_t khalf = (uint32_t)(lane >> 4);

#define CSTEP(stg, ks)                                                         \
    do {                                                                       \
        uint32_t sb0 = smem + (stg) * STG2;                                    \
        uint32_t pa = (((ks) * 2 + khalf) ^ lmask) * 16u;                      \
        uint32_t a[2][4], b[2][4];                                             \
        _Pragma("unroll") for (int mt = 0; mt < 2; ++mt)                       \
            ldmx4(a[mt], sb0 + rowA[mt] + pa);                                 \
        _Pragma("unroll") for (int i = 0; i < 2; ++i)                          \
            ldmx4(b[i], sb0 + rowB[i] + pa);                                   \
        _Pragma("unroll") for (int mt = 0; mt < 2; ++mt)                       \
            _Pragma("unroll") for (int j = 0; j < 4; ++j)                      \
                mma16816(acc[mt][j], a[mt], b[j >> 1][j & 1],                  \
                         b[j >> 1][2 + (j & 1)]);                              \
    } while (0)

    const int T = NROWS / BK2;  // 128

    // prologue: fill tiles 0..2 (stages 0..2); preload pf for tile 3
    LDGA(0); STSA(0); CPB(0, 0); cp_commit();
    LDGA(1); STSA(1); CPB(1, 1); cp_commit();
    LDGA(2); STSA(2); CPB(2, 2); cp_commit();
    LDGA(3);                                  // pf <- tile 3 (consumed iter 0)
    cp_wait0();
    __syncwarp();
    if (elect_one()) {
        mbar_arrive(mb + 0);
        mbar_arrive(mb + 16);
        mbar_arrive(mb + 32);
    }

    for (int t = 0; t < T; ++t) {
        const int s  = t & 3;
        const int tp = t + 3;
        const int sp = tp & 3;

        mbar_wait(mb + 16 * s, (uint32_t)((t >> 2) & 1));   // full[s]

        CSTEP(s, 0);
        CSTEP(s, 1);

        if (tp < T) {
            if (tp >= NSTG)
                mbar_wait(mb + 16 * sp + 8, (uint32_t)(((tp >> 2) - 1) & 1));
            STSA(sp);                         // pf holds tile tp (prev iter)
            CPB(sp, tp);
        }
        cp_commit();   // one group per iteration, possibly empty

        if (tp + 1 < T) LDGA(tp + 1);         // pf <- tile tp+1 (next iter)

        CSTEP(s, 2);
        CSTEP(s, 3);

        __syncwarp();
        if (elect_one()) mbar_arrive(mb + 16 * s + 8);      // empty[s]

        // publish previous iteration's fill (tile t+2) once own cps drained
        if (t >= 1 && t + 2 < T) {
            cp_wait1();
            __syncwarp();
            if (elect_one()) mbar_arrive(mb + 16 * ((t + 2) & 3));
        }
    }

    // epilogue -> out directly, scaled by d[m]
    const int er = lane >> 2;
    const int ec = (lane & 3) * 2;
#pragma unroll
    for (int mt = 0; mt < 2; ++mt) {
        const int lr = wm + mt * 16 + er;
        const int r0 = m0 + lr;
        const float s0 = s_d[lr], s1 = s_d[lr + 8];
#pragma unroll
        for (int j = 0; j < 4; ++j) {
            const int c = n0 + wn + j * 8 + ec;
            float* a = acc[mt][j];
            *(float2*)(out + (size_t)r0 * NCH + c) =
                make_float2(s0 * a[0], s0 * a[1]);
            *(float2*)(out + (size_t)(r0 + 8) * NCH + c) =
                make_float2(s1 * a[2], s1 * a[3]);
        }
    }
#undef LDGA
#undef STSA
#undef CPB
#undef CSTEP
}

// ---------------- launch ----------------
extern "C" void kernel_launch(void* const* d_in, const int* in_sizes, int n_in,
                              void* d_out, int out_size) {
    (void)in_sizes; (void)n_in; (void)out_size;
    const float* A = (const float*)d_in[0];
    const float* D = (const float*)d_in[1];
    const float* H = (const float*)d_in[2];
    const float* W = (const float*)d_in[3];
    float* out = (float*)d_out;

    __half *pWhT, *pBhT;
    cudaGetSymbolAddress((void**)&pWhT, g_WhT);
    cudaGetSymbolAddress((void**)&pBhT, g_BhT);

    cudaFuncSetAttribute(gemm1_hmma, cudaFuncAttributeMaxDynamicSharedMemorySize,
                         SMEM_SZ);
    cudaFuncSetAttribute(gemm2_hmma, cudaFuncAttributeMaxDynamicSharedMemorySize,
                         SMEM2);

    // W^T fp16 (coalesced shared-tile transpose)
    transposeW_kernel<<<64, 256>>>(W);

    // BhT[n][m] = d[m] * (W^T @ H^T)[n][m]   (d self-computed per CTA)
    gemm1_hmma<<<dim3(NROWS / BN, NCH / BM), NTHREADS, SMEM_SZ>>>(
        H, NCH, pWhT, NCH, NCH / BK, pBhT, D);

    // out = diag(d) * (A @ B)  — full K per CTA, N-split, direct store
    gemm2_hmma<<<dim3(NROWS / BM2, NCH / BN2), NTH2, SMEM2>>>(A, D, out);
}

// round 16
// speedup vs baseline: 1.0275x; 1.0275x over previous
#include <cuda_runtime.h>
#include <cuda_fp16.h>
#include <cstdint>

#define NROWS 8192
#define NCH   256

// ---- GEMM1 (small) tiling ----
#define BM 128
#define BN 128
#define BK 64
#define NTHREADS 256
#define STAGE_BYTES 32768
#define SMEM_SZ (2 * STAGE_BYTES)

// ---- GEMM2 (big) tiling ----
#define BM2 128
#define BN2 256
#define BK2 64
#define NTH2 512
#define KSPLIT 2
#define KLEN (NROWS / KSPLIT)      // 4096
#define NSTG 4
#define STG2 49152                 // A 16KB + B 32KB
#define SMEM2 (NSTG * STG2 + 128)  // stages + mbarriers

// ---------------- device scratch ----------------
__device__ __half g_WhT[NCH * NCH];            // W^T fp16 [n][k]
__device__ __half g_BhT[(size_t)NCH * NROWS];  // B^T fp16 [n][m]
__device__ float  g_P[(size_t)KSPLIT * NROWS * NCH];  // K-split partials

// ---------------- PTX helpers ----------------
__device__ __forceinline__ uint32_t cvta_smem(const void* p) {
    uint32_t a;
    asm("{ .reg .u64 t; cvta.to.shared.u64 t, %1; cvt.u32.u64 %0, t; }"
        : "=r"(a) : "l"(p));
    return a;
}
__device__ __forceinline__ uint32_t elect_one() {
    uint32_t r;
    asm volatile("{ .reg .pred p; elect.sync _|p, 0xFFFFFFFF; selp.b32 %0,1,0,p; }"
                 : "=r"(r));
    return r;
}
__device__ __forceinline__ void cp16(uint32_t saddr, const void* gaddr) {
    asm volatile("cp.async.cg.shared.global [%0], [%1], 16;"
                 :: "r"(saddr), "l"(gaddr) : "memory");
}
__device__ __forceinline__ void cp_commit() {
    asm volatile("cp.async.commit_group;" ::: "memory");
}
__device__ __forceinline__ void cp_wait0() {
    asm volatile("cp.async.wait_group 0;" ::: "memory");
}
__device__ __forceinline__ void cp_wait1() {
    asm volatile("cp.async.wait_group 1;" ::: "memory");
}
__device__ __forceinline__ void mbar_init(uint32_t m, uint32_t cnt) {
    asm volatile("mbarrier.init.shared.b64 [%0], %1;" :: "r"(m), "r"(cnt) : "memory");
}
__device__ __forceinline__ void mbar_arrive(uint32_t m) {
    asm volatile("{ .reg .b64 st; mbarrier.arrive.shared.b64 st, [%0]; }"
                 :: "r"(m) : "memory");
}
__device__ __forceinline__ void mbar_wait(uint32_t m, uint32_t parity) {
    asm volatile(
        "{\n\t.reg .pred P;\n"
        "LW_%=:\n\t"
        "mbarrier.try_wait.parity.acquire.cta.shared::cta.b64 P, [%0], %1, 0x989680;\n\t"
        "@P bra.uni LD_%=;\n\t"
        "bra.uni LW_%=;\n"
        "LD_%=:\n\t}"
        :: "r"(m), "r"(parity) : "memory");
}
__device__ __forceinline__ void ldmx4(uint32_t* r, uint32_t addr) {
    asm volatile("ldmatrix.sync.aligned.m8n8.x4.shared.b16 {%0,%1,%2,%3}, [%4];"
                 : "=r"(r[0]), "=r"(r[1]), "=r"(r[2]), "=r"(r[3]) : "r"(addr));
}
__device__ __forceinline__ void mma16816(float* c, const uint32_t* a,
                                         uint32_t b0, uint32_t b1) {
    asm volatile(
        "mma.sync.aligned.m16n8k16.row.col.f32.f16.f16.f32 "
        "{%0,%1,%2,%3}, {%4,%5,%6,%7}, {%8,%9}, {%0,%1,%2,%3};"
        : "+f"(c[0]), "+f"(c[1]), "+f"(c[2]), "+f"(c[3])
        : "r"(a[0]), "r"(a[1]), "r"(a[2]), "r"(a[3]), "r"(b0), "r"(b1));
}
__device__ __forceinline__ void sts128(uint32_t addr, uint32_t x, uint32_t y,
                                       uint32_t z, uint32_t w) {
    asm volatile("st.shared.v4.b32 [%0], {%1,%2,%3,%4};"
                 :: "r"(addr), "r"(x), "r"(y), "r"(z), "r"(w) : "memory");
}
// refined rsqrt of D's diagonal element i
__device__ __forceinline__ float dval(const float* __restrict__ D, int i) {
    float x = D[(size_t)i * (NROWS + 1)];
    float r = rsqrtf(x);
    return r * (1.5f - 0.5f * x * r * r);
}

// ---------------- W^T transpose (coalesced both ways) ----------------
__global__ void transposeW_kernel(const float* __restrict__ W) {
    __shared__ float tile[32][33];
    const int bx = blockIdx.x & 7;    // n-tile
    const int by = blockIdx.x >> 3;   // k-tile
    const int x  = threadIdx.x & 31;
    const int y0 = (threadIdx.x >> 5) * 4;
#pragma unroll
    for (int i = 0; i < 4; ++i)
        tile[y0 + i][x] = W[(by * 32 + y0 + i) * NCH + bx * 32 + x];
    __syncthreads();
#pragma unroll
    for (int i = 0; i < 4; ++i)
        g_WhT[(bx * 32 + y0 + i) * NCH + by * 32 + x] =
            __float2half_rn(tile[x][y0 + i]);
}

// out[m][n] = d[m] * (P0[m][n] + P1[m][n]);  d computed inline (L2-hot)
__global__ void reduce_kernel(const float* __restrict__ D,
                              float* __restrict__ out) {
    size_t base = ((size_t)blockIdx.x * blockDim.x + threadIdx.x) * 4;
    int row = (int)(base >> 8);
    float sc = dval(D, row);
    float4 a = *(const float4*)(g_P + base);
    float4 b = *(const float4*)(g_P + (size_t)NROWS * NCH + base);
    float4 o;
    o.x = sc * (a.x + b.x);
    o.y = sc * (a.y + b.y);
    o.z = sc * (a.z + b.z);
    o.w = sc * (a.w + b.w);
    *(float4*)(out + base) = o;
}

// ---------------------------------------------------------------------------
// GEMM1 (2-stage lockstep): BhT[n][m] = d[m]*(W^T @ H^T)[n][m]
// ---------------------------------------------------------------------------
__global__ __launch_bounds__(NTHREADS, 1)
void gemm1_hmma(const float* __restrict__ f32op, int ld32,
                const __half* __restrict__ f16op, int ld16,
                int ktiles, __half* __restrict__ dsth,
                const float* __restrict__ D) {
    extern __shared__ __align__(16) char smem_raw[];
    __shared__ float s_d[BN];
    const uint32_t smem = cvta_smem(smem_raw);

    const int tid  = threadIdx.x;
    const int lane = tid & 31;
    const int wid  = tid >> 5;
    const int wm   = (wid & 1) * 64;
    const int wn   = (wid >> 1) * 32;

    const int m0 = blockIdx.y * BM;   // n-channel dim
    const int n0 = blockIdx.x * BN;   // node dim

    if (tid < BN) s_d[tid] = dval(D, n0 + tid);

    const uint32_t off32 = 16384u;
    const uint32_t off16 = 0u;

    const int lrow = tid >> 1;
    const int lseg = tid & 1;
    const float* g32 = f32op + (size_t)(n0 + lrow) * ld32 + lseg * 32;
    const __half* g16 = f16op + (size_t)(m0 + lrow) * ld16 + lseg * 32;
    const uint32_t srow = (uint32_t)lrow * 128u;
    const int rmask = lrow & 7;

    float4 pf[8];

#define LDG32(t)                                                               \
    do {                                                                       \
        const float4* p = (const float4*)(g32 + (size_t)(t) * BK);             \
        _Pragma("unroll") for (int j = 0; j < 8; ++j) pf[j] = __ldg(p + j);    \
    } while (0)
#define STS32(stg)                                                             \
    do {                                                                       \
        uint32_t db = smem + (stg) * STAGE_BYTES + off32 + srow;               \
        _Pragma("unroll") for (int c = 0; c < 4; ++c) {                        \
            __half2 h0 = __floats2half2_rn(pf[2 * c].x, pf[2 * c].y);          \
            __half2 h1 = __floats2half2_rn(pf[2 * c].z, pf[2 * c].w);          \
            __half2 h2 = __floats2half2_rn(pf[2 * c + 1].x, pf[2 * c + 1].y);  \
            __half2 h3 = __floats2half2_rn(pf[2 * c + 1].z, pf[2 * c + 1].w);  \
            uint32_t ch = (uint32_t)((lseg * 4 + c) ^ rmask);                  \
            sts128(db + ch * 16u, *(uint32_t*)&h0, *(uint32_t*)&h1,            \
                   *(uint32_t*)&h2, *(uint32_t*)&h3);                          \
        }                                                                      \
    } while (0)
#define CP16T(t, stg)                                                          \
    do {                                                                       \
        uint32_t db = smem + (stg) * STAGE_BYTES + off16 + srow;               \
        const __half* p = g16 + (size_t)(t) * BK;                              \
        _Pragma("unroll") for (int j = 0; j < 4; ++j) {                        \
            uint32_t ch = (uint32_t)((lseg * 4 + j) ^ rmask);                  \
            cp16(db + ch * 16u, p + j * 8);                                    \
        }                                                                      \
    } while (0)

    float acc[4][4][4];
#pragma unroll
    for (int i = 0; i < 4; ++i)
#pragma unroll
        for (int j = 0; j < 4; ++j)
#pragma unroll
            for (int q = 0; q < 4; ++q) acc[i][j][q] = 0.0f;

    const int lr8 = (lane & 7) + ((lane >> 3) & 1) * 8;
    uint32_t rowA[4], rowB[2];
#pragma unroll
    for (int mt = 0; mt < 4; ++mt) rowA[mt] = (uint32_t)(wm + mt * 16 + lr8) * 128u;
#pragma unroll
    for (int i = 0; i < 2; ++i) rowB[i] = (uint32_t)(wn + i * 16 + lr8) * 128u;
    const uint32_t lmask = (uint32_t)(lane & 7);
    const uint32_t khalf = (uint32_t)(lane >> 4);

#define COMPUTE1(stg)                                                          \
    do {                                                                       \
        uint32_t sa = smem + (stg) * STAGE_BYTES + off16;                      \
        uint32_t sb = smem + (stg) * STAGE_BYTES + off32;                      \
        _Pragma("unroll") for (int ks = 0; ks < 4; ++ks) {                     \
            uint32_t pa = ((ks * 2 + khalf) ^ lmask) * 16u;                    \
            uint32_t a[4][4], b[2][4];                                         \
            _Pragma("unroll") for (int mt = 0; mt < 4; ++mt)                   \
                ldmx4(a[mt], sa + rowA[mt] + pa);                              \
            _Pragma("unroll") for (int i = 0; i < 2; ++i)                      \
                ldmx4(b[i], sb + rowB[i] + pa);                                \
            _Pragma("unroll") for (int mt = 0; mt < 4; ++mt)                   \
                _Pragma("unroll") for (int j = 0; j < 4; ++j)                  \
                    mma16816(acc[mt][j], a[mt], b[j >> 1][j & 1],              \
                             b[j >> 1][2 + (j & 1)]);                          \
        }                                                                      \
    } while (0)

    const int T = ktiles;
    LDG32(0);
    CP16T(0, 0);
    cp_commit();
    STS32(0);
    if (T > 1) LDG32(1);
    cp_wait0();
    __syncthreads();

    int s = 0;
    for (int t = 0; t < T; ++t) {
        if (t + 1 < T) { CP16T(t + 1, s ^ 1); cp_commit(); }
        COMPUTE1(s);
        if (t + 1 < T) {
            STS32(s ^ 1);
            if (t + 2 < T) LDG32(t + 2);
            cp_wait0();
        }
        __syncthreads();
        s ^= 1;
    }

    const int er = lane >> 2;
    const int ec = (lane & 3) * 2;
#pragma unroll
    for (int mt = 0; mt < 4; ++mt) {
        const int r0 = m0 + wm + mt * 16 + er;
#pragma unroll
        for (int j = 0; j < 4; ++j) {
            const int cl = wn + j * 8 + ec;         // local node col in [0,BN)
            const int c  = n0 + cl;
            float* a = acc[mt][j];
            float s0 = s_d[cl], s1 = s_d[cl + 1];
            __half2 h0 = __floats2half2_rn(a[0] * s0, a[1] * s1);
            __half2 h1 = __floats2half2_rn(a[2] * s0, a[3] * s1);
            *(__half2*)(dsth + (size_t)r0 * NROWS + c) = h0;
            *(__half2*)(dsth + (size_t)(r0 + 8) * NROWS + c) = h1;
        }
    }
#undef LDG32
#undef STS32
#undef CP16T
#undef COMPUTE1
}

// ---------------------------------------------------------------------------
// GEMM2: CTA 128x256, 512 threads, 16 warps of 64x32, 4-stage mbarrier
// pipeline. Loader work (STSA/CPB/LDGA) hoisted BEFORE the full[s] wait so it
// executes in the wait shadow; the 4 CSTEPs run back-to-back afterward.
// Writes fp32 partials to g_P.
// ---------------------------------------------------------------------------
__global__ __launch_bounds__(NTH2, 1)
void gemm2_hmma(const float* __restrict__ A, float* __restrict__ P) {
    extern __shared__ __align__(16) char smem_raw[];
    const uint32_t smem = cvta_smem(smem_raw);
    const uint32_t mb = smem + NSTG * STG2;   // full[s]=mb+16s, empty[s]=+16s+8

    const int tid  = threadIdx.x;
    const int lane = tid & 31;
    const int wid  = tid >> 5;               // 0..15
    const int wm   = (wid & 1) * 64;         // 2 warps in M
    const int wn   = (wid >> 1) * 32;        // 8 warps in N

    const int m0 = blockIdx.x * BM2;
    const int kb = blockIdx.y * KLEN;

    if (tid == 0) {
#pragma unroll
        for (int s = 0; s < NSTG; ++s) {
            mbar_init(mb + 16 * s, 16);      // full: 16 warp arrivals
            mbar_init(mb + 16 * s + 8, 16);  // empty: 16 warp arrivals
        }
    }
    __syncthreads();

    // A loader: 4 threads/row, each 16 floats (4 x float4)
    const int arow = tid >> 2;               // 0..127
    const int aq   = tid & 3;
    const float* gA = A + (size_t)(m0 + arow) * NROWS + kb + aq * 16;
    const uint32_t arow_off = (uint32_t)arow * 128u;
    const int armask = arow & 7;

    // B loader: 2 threads/row (256 rows), 4 x 16B chunks each
    const int brow = tid >> 1;               // 0..255
    const int bh   = tid & 1;
    const __half* gB = g_BhT + (size_t)brow * NROWS + kb + bh * 32;
    const uint32_t brow_off = 16384u + (uint32_t)brow * 128u;
    const int brmask = brow & 7;

    float4 pf[4];

#define LDGA(t)                                                                \
    do {                                                                       \
        const float4* p = (const float4*)(gA + (size_t)(t) * BK2);             \
        _Pragma("unroll") for (int j = 0; j < 4; ++j) pf[j] = __ldg(p + j);    \
    } while (0)
#define STSA(stg)                                                              \
    do {                                                                       \
        uint32_t db = smem + (stg) * STG2 + arow_off;                          \
        _Pragma("unroll") for (int c = 0; c < 2; ++c) {                        \
            __half2 h0 = __floats2half2_rn(pf[2 * c].x, pf[2 * c].y);          \
            __half2 h1 = __floats2half2_rn(pf[2 * c].z, pf[2 * c].w);          \
            __half2 h2 = __floats2half2_rn(pf[2 * c + 1].x, pf[2 * c + 1].y);  \
            __half2 h3 = __floats2half2_rn(pf[2 * c + 1].z, pf[2 * c + 1].w);  \
            uint32_t ch = (uint32_t)((aq * 2 + c) ^ armask);                   \
            sts128(db + ch * 16u, *(uint32_t*)&h0, *(uint32_t*)&h1,            \
                   *(uint32_t*)&h2, *(uint32_t*)&h3);                          \
        }                                                                      \
    } while (0)
#define CPB(stg, t)                                                            \
    do {                                                                       \
        uint32_t db = smem + (stg) * STG2 + brow_off;                          \
        const __half* p = gB + (size_t)(t) * BK2;                              \
        _Pragma("unroll") for (int j = 0; j < 4; ++j) {                        \
            uint32_t ch = (uint32_t)((bh * 4 + j) ^ brmask);                   \
            cp16(db + ch * 16u, p + j * 8);                                    \
        }                                                                      \
    } while (0)

    float acc[4][4][4];
#pragma unroll
    for (int i = 0; i < 4; ++i)
#pragma unroll
        for (int j = 0; j < 4; ++j)
#pragma unroll
            for (int q = 0; q < 4; ++q) acc[i][j][q] = 0.0f;

    const int lr8 = (lane & 7) + ((lane >> 3) & 1) * 8;
    uint32_t rowA[4], rowB[2];
#pragma unroll
    for (int mt = 0; mt < 4; ++mt) rowA[mt] = (uint32_t)(wm + mt * 16 + lr8) * 128u;
#pragma unroll
    for (int i = 0; i < 2; ++i)
        rowB[i] = 16384u + (uint32_t)(wn + i * 16 + lr8) * 128u;
    const uint32_t lmask = (uint32_t)(lane & 7);
    const uint32_t khalf = (uint32_t)(lane >> 4);

#define CSTEP(stg, ks)                                                         \
    do {                                                                       \
        uint32_t sb0 = smem + (stg) * STG2;                                    \
        uint32_t pa = (((ks) * 2 + khalf) ^ lmask) * 16u;                      \
        uint32_t a[4][4], b[2][4];                                             \
        _Pragma("unroll") for (int mt = 0; mt < 4; ++mt)                       \
            ldmx4(a[mt], sb0 + rowA[mt] + pa);                                 \
        _Pragma("unroll") for (int i = 0; i < 2; ++i)                          \
            ldmx4(b[i], sb0 + rowB[i] + pa);                                   \
        _Pragma("unroll") for (int mt = 0; mt < 4; ++mt)                       \
            _Pragma("unroll") for (int j = 0; j < 4; ++j)                      \
                mma16816(acc[mt][j], a[mt], b[j >> 1][j & 1],                  \
                         b[j >> 1][2 + (j & 1)]);                              \
    } while (0)

    const int T = KLEN / BK2;  // 64

    // prologue: fill tiles 0..2 (stages 0..2); preload pf for tile 3
    LDGA(0); STSA(0); CPB(0, 0); cp_commit();
    LDGA(1); STSA(1); CPB(1, 1); cp_commit();
    LDGA(2); STSA(2); CPB(2, 2); cp_commit();
    LDGA(3);                                  // pf <- tile 3 (consumed iter 0)
    cp_wait0();
    __syncwarp();
    if (elect_one()) {
        mbar_arrive(mb + 0);
        mbar_arrive(mb + 16);
        mbar_arrive(mb + 32);
    }

    for (int t = 0; t < T; ++t) {
        const int s  = t & 3;
        const int tp = t + 3;
        const int sp = tp & 3;

        // ---- loader work first: runs in the shadow of the full[s] wait ----
        if (tp < T) {
            if (tp >= NSTG)
                mbar_wait(mb + 16 * sp + 8, (uint32_t)(((tp >> 2) - 1) & 1));
            STSA(sp);                         // pf holds tile tp (prev iter)
            CPB(sp, tp);
        }
        cp_commit();   // one group per iteration, possibly empty

        if (tp + 1 < T) LDGA(tp + 1);         // pf <- tile tp+1 (next iter)

        // ---- compute: 4 uninterrupted CSTEPs ----
        mbar_wait(mb + 16 * s, (uint32_t)((t >> 2) & 1));   // full[s]

        CSTEP(s, 0);
        CSTEP(s, 1);
        CSTEP(s, 2);
        CSTEP(s, 3);

        __syncwarp();
        if (elect_one()) mbar_arrive(mb + 16 * s + 8);      // empty[s]

        // publish previous iteration's fill (tile t+2) once own cps drained
        if (t >= 1 && t + 2 < T) {
            cp_wait1();
            __syncwarp();
            if (elect_one()) mbar_arrive(mb + 16 * ((t + 2) & 3));
        }
    }

    // epilogue -> fp32 partials
    float* Pz = P + (size_t)blockIdx.y * NROWS * NCH;
    const int er = lane >> 2;
    const int ec = (lane & 3) * 2;
#pragma unroll
    for (int mt = 0; mt < 4; ++mt) {
        const int r0 = m0 + wm + mt * 16 + er;
#pragma unroll
        for (int j = 0; j < 4; ++j) {
            const int c = wn + j * 8 + ec;
            float* a = acc[mt][j];
            *(float2*)(Pz + (size_t)r0 * NCH + c) = make_float2(a[0], a[1]);
            *(float2*)(Pz + (size_t)(r0 + 8) * NCH + c) = make_float2(a[2], a[3]);
        }
    }
#undef LDGA
#undef STSA
#undef CPB
#undef CSTEP
}

// ---------------- launch ----------------
extern "C" void kernel_launch(void* const* d_in, const int* in_sizes, int n_in,
                              void* d_out, int out_size) {
    (void)in_sizes; (void)n_in; (void)out_size;
    const float* A = (const float*)d_in[0];
    const float* D = (const float*)d_in[1];
    const float* H = (const float*)d_in[2];
    const float* W = (const float*)d_in[3];
    float* out = (float*)d_out;

    __half *pWhT, *pBhT;
    float* pP;
    cudaGetSymbolAddress((void**)&pWhT, g_WhT);
    cudaGetSymbolAddress((void**)&pBhT, g_BhT);
    cudaGetSymbolAddress((void**)&pP, g_P);

    cudaFuncSetAttribute(gemm1_hmma, cudaFuncAttributeMaxDynamicSharedMemorySize,
                         SMEM_SZ);
    cudaFuncSetAttribute(gemm2_hmma, cudaFuncAttributeMaxDynamicSharedMemorySize,
                         SMEM2);

    // W^T fp16 (coalesced shared-tile transpose)
    transposeW_kernel<<<64, 256>>>(W);

    // BhT[n][m] = d[m] * (W^T @ H^T)[n][m]   (d self-computed per CTA)
    gemm1_hmma<<<dim3(NROWS / BN, NCH / BM), NTHREADS, SMEM_SZ>>>(
        H, NCH, pWhT, NCH, NCH / BK, pBhT, D);

    // P[z] = A[:, z-slice] @ B[z-slice, :]
    gemm2_hmma<<<dim3(NROWS / BM2, KSPLIT), NTH2, SMEM2>>>(A, pP);

    // out = diag(d) * (P0 + P1)   (d computed inline)
    reduce_kernel<<<(NROWS * NCH) / 1024, 256>>>(D, out);
}

// round 17
// speedup vs baseline: 1.3294x; 1.2939x over previous
#include <cuda_runtime.h>
#include <cuda_fp16.h>
#include <cstdint>

#define NROWS 8192
#define NCH   256

// ---- GEMM1 (small) tiling ----
#define BM 128
#define BN 128
#define BK 64
#define NTHREADS 256
#define STAGE_BYTES 32768
#define SMEM_SZ (2 * STAGE_BYTES)

// ---- GEMM2 (big) tiling ----
#define BM2 128
#define BN2 256
#define BK2 64
#define NTH2 512
#define KSPLIT 2
#define KLEN (NROWS / KSPLIT)      // 4096
#define NSTG 4
#define STG2 49152                 // A 16KB + B 32KB
#define SMEM2 (NSTG * STG2 + 128)  // stages + mbarriers

// ---------------- device scratch ----------------
__device__ __half g_WhT[NCH * NCH];            // W^T fp16 [n][k]
__device__ __half g_BhT[(size_t)NCH * NROWS];  // B^T fp16 [n][m]
__device__ float  g_P[(size_t)KSPLIT * NROWS * NCH];  // K-split partials

// ---------------- PTX helpers ----------------
__device__ __forceinline__ uint32_t cvta_smem(const void* p) {
    uint32_t a;
    asm("{ .reg .u64 t; cvta.to.shared.u64 t, %1; cvt.u32.u64 %0, t; }"
        : "=r"(a) : "l"(p));
    return a;
}
__device__ __forceinline__ uint32_t elect_one() {
    uint32_t r;
    asm volatile("{ .reg .pred p; elect.sync _|p, 0xFFFFFFFF; selp.b32 %0,1,0,p; }"
                 : "=r"(r));
    return r;
}
__device__ __forceinline__ void gdc_wait() {
    asm volatile("griddepcontrol.wait;" ::: "memory");
}
__device__ __forceinline__ void gdc_launch() {
    asm volatile("griddepcontrol.launch_dependents;" ::: "memory");
}
__device__ __forceinline__ void cp16(uint32_t saddr, const void* gaddr) {
    asm volatile("cp.async.cg.shared.global [%0], [%1], 16;"
                 :: "r"(saddr), "l"(gaddr) : "memory");
}
__device__ __forceinline__ void cp_commit() {
    asm volatile("cp.async.commit_group;" ::: "memory");
}
__device__ __forceinline__ void cp_wait0() {
    asm volatile("cp.async.wait_group 0;" ::: "memory");
}
__device__ __forceinline__ void cp_wait1() {
    asm volatile("cp.async.wait_group 1;" ::: "memory");
}
__device__ __forceinline__ void mbar_init(uint32_t m, uint32_t cnt) {
    asm volatile("mbarrier.init.shared.b64 [%0], %1;" :: "r"(m), "r"(cnt) : "memory");
}
__device__ __forceinline__ void mbar_arrive(uint32_t m) {
    asm volatile("{ .reg .b64 st; mbarrier.arrive.shared.b64 st, [%0]; }"
                 :: "r"(m) : "memory");
}
__device__ __forceinline__ void mbar_wait(uint32_t m, uint32_t parity) {
    asm volatile(
        "{\n\t.reg .pred P;\n"
        "LW_%=:\n\t"
        "mbarrier.try_wait.parity.acquire.cta.shared::cta.b64 P, [%0], %1, 0x989680;\n\t"
        "@P bra.uni LD_%=;\n\t"
        "bra.uni LW_%=;\n"
        "LD_%=:\n\t}"
        :: "r"(m), "r"(parity) : "memory");
}
__device__ __forceinline__ void ldmx4(uint32_t* r, uint32_t addr) {
    asm volatile("ldmatrix.sync.aligned.m8n8.x4.shared.b16 {%0,%1,%2,%3}, [%4];"
                 : "=r"(r[0]), "=r"(r[1]), "=r"(r[2]), "=r"(r[3]) : "r"(addr));
}
__device__ __forceinline__ void mma16816(float* c, const uint32_t* a,
                                         uint32_t b0, uint32_t b1) {
    asm volatile(
        "mma.sync.aligned.m16n8k16.row.col.f32.f16.f16.f32 "
        "{%0,%1,%2,%3}, {%4,%5,%6,%7}, {%8,%9}, {%0,%1,%2,%3};"
        : "+f"(c[0]), "+f"(c[1]), "+f"(c[2]), "+f"(c[3])
        : "r"(a[0]), "r"(a[1]), "r"(a[2]), "r"(a[3]), "r"(b0), "r"(b1));
}
__device__ __forceinline__ void sts128(uint32_t addr, uint32_t x, uint32_t y,
                                       uint32_t z, uint32_t w) {
    asm volatile("st.shared.v4.b32 [%0], {%1,%2,%3,%4};"
                 :: "r"(addr), "r"(x), "r"(y), "r"(z), "r"(w) : "memory");
}
// refined rsqrt of D's diagonal element i
__device__ __forceinline__ float dval(const float* __restrict__ D, int i) {
    float x = D[(size_t)i * (NROWS + 1)];
    float r = rsqrtf(x);
    return r * (1.5f - 0.5f * x * r * r);
}

// ---------------- W^T transpose (coalesced both ways) ----------------
__global__ void transposeW_kernel(const float* __restrict__ W) {
    __shared__ float tile[32][33];
    gdc_launch();                     // let gemm1 launch & prefetch H early
    const int bx = blockIdx.x & 7;    // n-tile
    const int by = blockIdx.x >> 3;   // k-tile
    const int x  = threadIdx.x & 31;
    const int y0 = (threadIdx.x >> 5) * 4;
#pragma unroll
    for (int i = 0; i < 4; ++i)
        tile[y0 + i][x] = W[(by * 32 + y0 + i) * NCH + bx * 32 + x];
    __syncthreads();
#pragma unroll
    for (int i = 0; i < 4; ++i)
        g_WhT[(bx * 32 + y0 + i) * NCH + by * 32 + x] =
            __float2half_rn(tile[x][y0 + i]);
}

// out[m][n] = d[m] * (P0[m][n] + P1[m][n]);  d computed inline (L2-hot)
__global__ void reduce_kernel(const float* __restrict__ D,
                              float* __restrict__ out) {
    size_t base = ((size_t)blockIdx.x * blockDim.x + threadIdx.x) * 4;
    int row = (int)(base >> 8);
    float sc = dval(D, row);
    float4 a = *(const float4*)(g_P + base);
    float4 b = *(const float4*)(g_P + (size_t)NROWS * NCH + base);
    float4 o;
    o.x = sc * (a.x + b.x);
    o.y = sc * (a.y + b.y);
    o.z = sc * (a.z + b.z);
    o.w = sc * (a.w + b.w);
    *(float4*)(out + base) = o;
}

// ---------------------------------------------------------------------------
// GEMM1 (2-stage lockstep): BhT[n][m] = d[m]*(W^T @ H^T)[n][m]
// PDL: prologue H-load/d-compute run BEFORE the dependency wait; g_WhT reads
// (cp.async) happen only after griddepcontrol.wait.
// ---------------------------------------------------------------------------
__global__ __launch_bounds__(NTHREADS, 1)
void gemm1_hmma(const float* __restrict__ f32op, int ld32,
                const __half* __restrict__ f16op, int ld16,
                int ktiles, __half* __restrict__ dsth,
                const float* __restrict__ D) {
    extern __shared__ __align__(16) char smem_raw[];
    __shared__ float s_d[BN];
    const uint32_t smem = cvta_smem(smem_raw);

    const int tid  = threadIdx.x;
    const int lane = tid & 31;
    const int wid  = tid >> 5;
    const int wm   = (wid & 1) * 64;
    const int wn   = (wid >> 1) * 32;

    const int m0 = blockIdx.y * BM;   // n-channel dim
    const int n0 = blockIdx.x * BN;   // node dim

    if (tid < BN) s_d[tid] = dval(D, n0 + tid);

    const uint32_t off32 = 16384u;
    const uint32_t off16 = 0u;

    const int lrow = tid >> 1;
    const int lseg = tid & 1;
    const float* g32 = f32op + (size_t)(n0 + lrow) * ld32 + lseg * 32;
    const __half* g16 = f16op + (size_t)(m0 + lrow) * ld16 + lseg * 32;
    const uint32_t srow = (uint32_t)lrow * 128u;
    const int rmask = lrow & 7;

    float4 pf[8];

#define LDG32(t)                                                               \
    do {                                                                       \
        const float4* p = (const float4*)(g32 + (size_t)(t) * BK);             \
        _Pragma("unroll") for (int j = 0; j < 8; ++j) pf[j] = __ldg(p + j);    \
    } while (0)
#define STS32(stg)                                                             \
    do {                                                                       \
        uint32_t db = smem + (stg) * STAGE_BYTES + off32 + srow;               \
        _Pragma("unroll") for (int c = 0; c < 4; ++c) {                        \
            __half2 h0 = __floats2half2_rn(pf[2 * c].x, pf[2 * c].y);          \
            __half2 h1 = __floats2half2_rn(pf[2 * c].z, pf[2 * c].w);          \
            __half2 h2 = __floats2half2_rn(pf[2 * c + 1].x, pf[2 * c + 1].y);  \
            __half2 h3 = __floats2half2_rn(pf[2 * c + 1].z, pf[2 * c + 1].w);  \
            uint32_t ch = (uint32_t)((lseg * 4 + c) ^ rmask);                  \
            sts128(db + ch * 16u, *(uint32_t*)&h0, *(uint32_t*)&h1,            \
                   *(uint32_t*)&h2, *(uint32_t*)&h3);                          \
        }                                                                      \
    } while (0)
#define CP16T(t, stg)                                                          \
    do {                                                                       \
        uint32_t db = smem + (stg) * STAGE_BYTES + off16 + srow;               \
        const __half* p = g16 + (size_t)(t) * BK;                              \
        _Pragma("unroll") for (int j = 0; j < 4; ++j) {                        \
            uint32_t ch = (uint32_t)((lseg * 4 + j) ^ rmask);                  \
            cp16(db + ch * 16u, p + j * 8);                                    \
        }                                                                      \
    } while (0)

    float acc[4][4][4];
#pragma unroll
    for (int i = 0; i < 4; ++i)
#pragma unroll
        for (int j = 0; j < 4; ++j)
#pragma unroll
            for (int q = 0; q < 4; ++q) acc[i][j][q] = 0.0f;

    const int lr8 = (lane & 7) + ((lane >> 3) & 1) * 8;
    uint32_t rowA[4], rowB[2];
#pragma unroll
    for (int mt = 0; mt < 4; ++mt) rowA[mt] = (uint32_t)(wm + mt * 16 + lr8) * 128u;
#pragma unroll
    for (int i = 0; i < 2; ++i) rowB[i] = (uint32_t)(wn + i * 16 + lr8) * 128u;
    const uint32_t lmask = (uint32_t)(lane & 7);
    const uint32_t khalf = (uint32_t)(lane >> 4);

#define COMPUTE1(stg)                                                          \
    do {                                                                       \
        uint32_t sa = smem + (stg) * STAGE_BYTES + off16;                      \
        uint32_t sb = smem + (stg) * STAGE_BYTES + off32;                      \
        _Pragma("unroll") for (int ks = 0; ks < 4; ++ks) {                     \
            uint32_t pa = ((ks * 2 + khalf) ^ lmask) * 16u;                    \
            uint32_t a[4][4], b[2][4];                                         \
            _Pragma("unroll") for (int mt = 0; mt < 4; ++mt)                   \
                ldmx4(a[mt], sa + rowA[mt] + pa);                              \
            _Pragma("unroll") for (int i = 0; i < 2; ++i)                      \
                ldmx4(b[i], sb + rowB[i] + pa);                                \
            _Pragma("unroll") for (int mt = 0; mt < 4; ++mt)                   \
                _Pragma("unroll") for (int j = 0; j < 4; ++j)                  \
                    mma16816(acc[mt][j], a[mt], b[j >> 1][j & 1],              \
                             b[j >> 1][2 + (j & 1)]);                          \
        }                                                                      \
    } while (0)

    const int T = ktiles;
    // --- independent prologue (H + D are inputs): runs under transposeW ---
    LDG32(0);
    STS32(0);
    if (T > 1) LDG32(1);

    gdc_wait();                      // g_WhT ready beyond this point
    gdc_launch();                    // let gemm2 launch & prefetch A

    CP16T(0, 0);
    cp_commit();
    cp_wait0();
    __syncthreads();

    int s = 0;
    for (int t = 0; t < T; ++t) {
        if (t + 1 < T) { CP16T(t + 1, s ^ 1); cp_commit(); }
        COMPUTE1(s);
        if (t + 1 < T) {
            STS32(s ^ 1);
            if (t + 2 < T) LDG32(t + 2);
            cp_wait0();
        }
        __syncthreads();
        s ^= 1;
    }

    const int er = lane >> 2;
    const int ec = (lane & 3) * 2;
#pragma unroll
    for (int mt = 0; mt < 4; ++mt) {
        const int r0 = m0 + wm + mt * 16 + er;
#pragma unroll
        for (int j = 0; j < 4; ++j) {
            const int cl = wn + j * 8 + ec;         // local node col in [0,BN)
            const int c  = n0 + cl;
            float* a = acc[mt][j];
            float s0 = s_d[cl], s1 = s_d[cl + 1];
            __half2 h0 = __floats2half2_rn(a[0] * s0, a[1] * s1);
            __half2 h1 = __floats2half2_rn(a[2] * s0, a[3] * s1);
            *(__half2*)(dsth + (size_t)r0 * NROWS + c) = h0;
            *(__half2*)(dsth + (size_t)(r0 + 8) * NROWS + c) = h1;
        }
    }
#undef LDG32
#undef STS32
#undef CP16T
#undef COMPUTE1
}

// ---------------------------------------------------------------------------
// GEMM2: CTA 128x256, 512 threads, 16 warps of 64x32, 4-stage mbarrier
// pipeline, full-iteration A prefetch distance (mainloop = proven 133.6us
// config, untouched). PDL: the A-side prologue (LDGA/STSA, input-only) runs
// BEFORE the dependency wait; CPB (g_BhT reads) only after.
// ---------------------------------------------------------------------------
__global__ __launch_bounds__(NTH2, 1)
void gemm2_hmma(const float* __restrict__ A, float* __restrict__ P) {
    extern __shared__ __align__(16) char smem_raw[];
    const uint32_t smem = cvta_smem(smem_raw);
    const uint32_t mb = smem + NSTG * STG2;   // full[s]=mb+16s, empty[s]=+16s+8

    const int tid  = threadIdx.x;
    const int lane = tid & 31;
    const int wid  = tid >> 5;               // 0..15
    const int wm   = (wid & 1) * 64;         // 2 warps in M
    const int wn   = (wid >> 1) * 32;        // 8 warps in N

    const int m0 = blockIdx.x * BM2;
    const int kb = blockIdx.y * KLEN;

    if (tid == 0) {
#pragma unroll
        for (int s = 0; s < NSTG; ++s) {
            mbar_init(mb + 16 * s, 16);      // full: 16 warp arrivals
            mbar_init(mb + 16 * s + 8, 16);  // empty: 16 warp arrivals
        }
    }
    __syncthreads();

    // A loader: 4 threads/row, each 16 floats (4 x float4)
    const int arow = tid >> 2;               // 0..127
    const int aq   = tid & 3;
    const float* gA = A + (size_t)(m0 + arow) * NROWS + kb + aq * 16;
    const uint32_t arow_off = (uint32_t)arow * 128u;
    const int armask = arow & 7;

    // B loader: 2 threads/row (256 rows), 4 x 16B chunks each
    const int brow = tid >> 1;               // 0..255
    const int bh   = tid & 1;
    const __half* gB = g_BhT + (size_t)brow * NROWS + kb + bh * 32;
    const uint32_t brow_off = 16384u + (uint32_t)brow * 128u;
    const int brmask = brow & 7;

    float4 pf[4];

#define LDGA(t)                                                                \
    do {                                                                       \
        const float4* p = (const float4*)(gA + (size_t)(t) * BK2);             \
        _Pragma("unroll") for (int j = 0; j < 4; ++j) pf[j] = __ldg(p + j);    \
    } while (0)
#define STSA(stg)                                                              \
    do {                                                                       \
        uint32_t db = smem + (stg) * STG2 + arow_off;                          \
        _Pragma("unroll") for (int c = 0; c < 2; ++c) {                        \
            __half2 h0 = __floats2half2_rn(pf[2 * c].x, pf[2 * c].y);          \
            __half2 h1 = __floats2half2_rn(pf[2 * c].z, pf[2 * c].w);          \
            __half2 h2 = __floats2half2_rn(pf[2 * c + 1].x, pf[2 * c + 1].y);  \
            __half2 h3 = __floats2half2_rn(pf[2 * c + 1].z, pf[2 * c + 1].w);  \
            uint32_t ch = (uint32_t)((aq * 2 + c) ^ armask);                   \
            sts128(db + ch * 16u, *(uint32_t*)&h0, *(uint32_t*)&h1,            \
                   *(uint32_t*)&h2, *(uint32_t*)&h3);                          \
        }                                                                      \
    } while (0)
#define CPB(stg, t)                                                            \
    do {                                                                       \
        uint32_t db = smem + (stg) * STG2 + brow_off;                          \
        const __half* p = gB + (size_t)(t) * BK2;                              \
        _Pragma("unroll") for (int j = 0; j < 4; ++j) {                        \
            uint32_t ch = (uint32_t)((bh * 4 + j) ^ brmask);                   \
            cp16(db + ch * 16u, p + j * 8);                                    \
        }                                                                      \
    } while (0)

    float acc[4][4][4];
#pragma unroll
    for (int i = 0; i < 4; ++i)
#pragma unroll
        for (int j = 0; j < 4; ++j)
#pragma unroll
            for (int q = 0; q < 4; ++q) acc[i][j][q] = 0.0f;

    const int lr8 = (lane & 7) + ((lane >> 3) & 1) * 8;
    uint32_t rowA[4], rowB[2];
#pragma unroll
    for (int mt = 0; mt < 4; ++mt) rowA[mt] = (uint32_t)(wm + mt * 16 + lr8) * 128u;
#pragma unroll
    for (int i = 0; i < 2; ++i)
        rowB[i] = 16384u + (uint32_t)(wn + i * 16 + lr8) * 128u;
    const uint32_t lmask = (uint32_t)(lane & 7);
    const uint32_t khalf = (uint32_t)(lane >> 4);

#define CSTEP(stg, ks)                                                         \
    do {                                                                       \
        uint32_t sb0 = smem + (stg) * STG2;                                    \
        uint32_t pa = (((ks) * 2 + khalf) ^ lmask) * 16u;                      \
        uint32_t a[4][4], b[2][4];                                             \
        _Pragma("unroll") for (int mt = 0; mt < 4; ++mt)                       \
            ldmx4(a[mt], sb0 + rowA[mt] + pa);                                 \
        _Pragma("unroll") for (int i = 0; i < 2; ++i)                          \
            ldmx4(b[i], sb0 + rowB[i] + pa);                                   \
        _Pragma("unroll") for (int mt = 0; mt < 4; ++mt)                       \
            _Pragma("unroll") for (int j = 0; j < 4; ++j)                      \
                mma16816(acc[mt][j], a[mt], b[j >> 1][j & 1],                  \
                         b[j >> 1][2 + (j & 1)]);                              \
    } while (0)

    const int T = KLEN / BK2;  // 64

    // --- independent A-side prologue (A is an input): overlaps gemm1 tail ---
    LDGA(0); STSA(0);
    LDGA(1); STSA(1);
    LDGA(2); STSA(2);
    LDGA(3);                                  // pf <- tile 3 (consumed iter 0)

    gdc_wait();                               // g_BhT ready beyond this point

    CPB(0, 0); cp_commit();
    CPB(1, 1); cp_commit();
    CPB(2, 2); cp_commit();
    cp_wait0();
    __syncwarp();
    if (elect_one()) {
        mbar_arrive(mb + 0);
        mbar_arrive(mb + 16);
        mbar_arrive(mb + 32);
    }

    for (int t = 0; t < T; ++t) {
        const int s  = t & 3;
        const int tp = t + 3;
        const int sp = tp & 3;

        mbar_wait(mb + 16 * s, (uint32_t)((t >> 2) & 1));   // full[s]

        CSTEP(s, 0);
        CSTEP(s, 1);

        if (tp < T) {
            if (tp >= NSTG)
                mbar_wait(mb + 16 * sp + 8, (uint32_t)(((tp >> 2) - 1) & 1));
            STSA(sp);                         // pf holds tile tp (prev iter)
            CPB(sp, tp);
        }
        cp_commit();   // one group per iteration, possibly empty

        if (tp + 1 < T) LDGA(tp + 1);         // pf <- tile tp+1 (next iter)

        CSTEP(s, 2);
        CSTEP(s, 3);

        __syncwarp();
        if (elect_one()) mbar_arrive(mb + 16 * s + 8);      // empty[s]

        // publish previous iteration's fill (tile t+2) once own cps drained
        if (t >= 1 && t + 2 < T) {
            cp_wait1();
            __syncwarp();
            if (elect_one()) mbar_arrive(mb + 16 * ((t + 2) & 3));
        }
    }

    // epilogue -> fp32 partials
    float* Pz = P + (size_t)blockIdx.y * NROWS * NCH;
    const int er = lane >> 2;
    const int ec = (lane & 3) * 2;
#pragma unroll
    for (int mt = 0; mt < 4; ++mt) {
        const int r0 = m0 + wm + mt * 16 + er;
#pragma unroll
        for (int j = 0; j < 4; ++j) {
            const int c = wn + j * 8 + ec;
            float* a = acc[mt][j];
            *(float2*)(Pz + (size_t)r0 * NCH + c) = make_float2(a[0], a[1]);
            *(float2*)(Pz + (size_t)(r0 + 8) * NCH + c) = make_float2(a[2], a[3]);
        }
    }
#undef LDGA
#undef STSA
#undef CPB
#undef CSTEP
}

// ---------------- launch ----------------
extern "C" void kernel_launch(void* const* d_in, const int* in_sizes, int n_in,
                              void* d_out, int out_size) {
    (void)in_sizes; (void)n_in; (void)out_size;
    const float* A = (const float*)d_in[0];
    const float* D = (const float*)d_in[1];
    const float* H = (const float*)d_in[2];
    const float* W = (const float*)d_in[3];
    float* out = (float*)d_out;

    __half *pWhT, *pBhT;
    float* pP;
    cudaGetSymbolAddress((void**)&pWhT, g_WhT);
    cudaGetSymbolAddress((void**)&pBhT, g_BhT);
    cudaGetSymbolAddress((void**)&pP, g_P);

    cudaFuncSetAttribute(gemm1_hmma, cudaFuncAttributeMaxDynamicSharedMemorySize,
                         SMEM_SZ);
    cudaFuncSetAttribute(gemm2_hmma, cudaFuncAttributeMaxDynamicSharedMemorySize,
                         SMEM2);

    // W^T fp16 (coalesced shared-tile transpose); triggers gemm1 early-launch
    transposeW_kernel<<<64, 256>>>(W);

    cudaLaunchAttribute pdl[1];
    pdl[0].id = cudaLaunchAttributeProgrammaticStreamSerialization;
    pdl[0].val.programmaticStreamSerializationAllowed = 1;

    // gemm1: PDL consumer of transposeW (prefetches H before the wait)
    {
        cudaLaunchConfig_t cfg = {};
        cfg.gridDim = dim3(NROWS / BN, NCH / BM);
        cfg.blockDim = dim3(NTHREADS);
        cfg.dynamicSmemBytes = SMEM_SZ;
        cfg.stream = 0;
        cfg.attrs = pdl;
        cfg.numAttrs = 1;
        cudaLaunchKernelEx(&cfg, gemm1_hmma, H, NCH, (const __half*)pWhT, NCH,
                           NCH / BK, pBhT, D);
    }

    // gemm2: PDL consumer of gemm1 (prefetches A before the wait)
    {
        cudaLaunchConfig_t cfg = {};
        cfg.gridDim = dim3(NROWS / BM2, KSPLIT);
        cfg.blockDim = dim3(NTH2);
        cfg.dynamicSmemBytes = SMEM2;
        cfg.stream = 0;
        cfg.attrs = pdl;
        cfg.numAttrs = 1;
        cudaLaunchKernelEx(&cfg, gemm2_hmma, A, pP);
    }

    // out = diag(d) * (P0 + P1)   (normal launch; no PDL)
    reduce_kernel<<<(NROWS * NCH) / 1024, 256>>>(D, out);
}